// round 1
// baseline (speedup 1.0000x reference)
#include <cuda_runtime.h>
#include <math.h>

// Problem constants
#define B_SZ    4096
#define N_IN    7
#define PC_DIM  256
#define K_CAPS  25
#define MC_DIM  128
#define KM      (K_CAPS * MC_DIM)      // 3200
#define VOTES_PER_B (N_IN * KM)        // 22400
#define POSE_STRIDE (N_IN * PC_DIM)    // 1792
#define LN_EPS  1e-5f
#define AGREE_SCALE 0.08838834764831845f   // 1/sqrt(128)

// 367 MB scratch for votes[b][n][k][m]
__device__ float g_votes[(size_t)B_SZ * VOTES_PER_B];

// ---------------------------------------------------------------------------
// Kernel A: votes[b,n,k*128+m] = sum_d poses[b,n,d] * w[n,d,k,m]
// 7 GEMMs [4096,256] @ [256,3200], fp32 SIMT, 128x128 tile, BK=16, 8x8/thread
// grid (25, 32, 7), 256 threads
// ---------------------------------------------------------------------------
__global__ __launch_bounds__(256) void votes_kernel(
    const float* __restrict__ poses,
    const float* __restrict__ w)
{
    const int n  = blockIdx.z;
    const int tm = blockIdx.y;   // 0..31  (b tile)
    const int tn = blockIdx.x;   // 0..24  (km tile)

    __shared__ float sA[2][16][132];   // [k][m], padded
    __shared__ float sB[2][16][128];   // [k][n]

    const int tid = threadIdx.x;

    const float* Ab = poses + (size_t)tm * 128 * POSE_STRIDE + n * PC_DIM;
    const float* Bb = w + (size_t)n * PC_DIM * KM + tn * 128;

    // staging index decomposition
    const int a_row0 = tid >> 2;   // 0..63 (second half +64)
    const int a_c4   = tid & 3;    // which float4 within 16-wide k chunk
    const int b_row0 = tid >> 5;   // 0..7 (second +8)
    const int b_c4   = tid & 31;   // float4 within 128 cols

    float4 ra0, ra1, rb0, rb1;

    auto load_chunk = [&](int kc) {
        const float* pA = Ab + a_row0 * POSE_STRIDE + kc * 16 + a_c4 * 4;
        ra0 = *(const float4*)pA;
        ra1 = *(const float4*)(pA + 64 * POSE_STRIDE);
        const float* pB = Bb + (size_t)(kc * 16 + b_row0) * KM + b_c4 * 4;
        rb0 = *(const float4*)pB;
        rb1 = *(const float4*)(pB + 8 * KM);
    };
    auto store_chunk = [&](int buf) {
        sA[buf][a_c4*4+0][a_row0]    = ra0.x;
        sA[buf][a_c4*4+1][a_row0]    = ra0.y;
        sA[buf][a_c4*4+2][a_row0]    = ra0.z;
        sA[buf][a_c4*4+3][a_row0]    = ra0.w;
        sA[buf][a_c4*4+0][a_row0+64] = ra1.x;
        sA[buf][a_c4*4+1][a_row0+64] = ra1.y;
        sA[buf][a_c4*4+2][a_row0+64] = ra1.z;
        sA[buf][a_c4*4+3][a_row0+64] = ra1.w;
        *(float4*)&sB[buf][b_row0][b_c4*4]     = rb0;
        *(float4*)&sB[buf][b_row0+8][b_c4*4]   = rb1;
    };

    // compute-thread mapping: warp = 4(M) x 2(N); in-warp 4(M) x 8(N)
    const int lane = tid & 31, wrp = tid >> 5;
    const int wm = wrp >> 1, wn = wrp & 1;
    const int row0 = wm * 32 + (lane >> 3) * 8;   // 0..120
    const int col0 = wn * 64 + (lane & 7) * 8;    // 0..120

    float acc[8][8];
    #pragma unroll
    for (int i = 0; i < 8; i++)
        #pragma unroll
        for (int j = 0; j < 8; j++) acc[i][j] = 0.f;

    load_chunk(0);
    store_chunk(0);
    __syncthreads();

    #pragma unroll 1
    for (int kc = 0; kc < 16; ++kc) {
        const int buf = kc & 1;
        if (kc < 15) load_chunk(kc + 1);
        #pragma unroll
        for (int kk = 0; kk < 16; ++kk) {
            float4 a0 = *(const float4*)&sA[buf][kk][row0];
            float4 a1 = *(const float4*)&sA[buf][kk][row0 + 4];
            float4 b0 = *(const float4*)&sB[buf][kk][col0];
            float4 b1 = *(const float4*)&sB[buf][kk][col0 + 4];
            float av[8] = {a0.x, a0.y, a0.z, a0.w, a1.x, a1.y, a1.z, a1.w};
            float bv[8] = {b0.x, b0.y, b0.z, b0.w, b1.x, b1.y, b1.z, b1.w};
            #pragma unroll
            for (int i = 0; i < 8; i++)
                #pragma unroll
                for (int j = 0; j < 8; j++)
                    acc[i][j] = fmaf(av[i], bv[j], acc[i][j]);
        }
        if (kc < 15) {
            __syncthreads();
            store_chunk(buf ^ 1);
            __syncthreads();
        }
    }

    // epilogue: votes[b][n][col]
    float* outp = g_votes + (size_t)(tm * 128 + row0) * VOTES_PER_B
                + n * KM + tn * 128 + col0;
    #pragma unroll
    for (int i = 0; i < 8; i++) {
        float4 v0 = make_float4(acc[i][0], acc[i][1], acc[i][2], acc[i][3]);
        float4 v1 = make_float4(acc[i][4], acc[i][5], acc[i][6], acc[i][7]);
        *(float4*)(outp + (size_t)i * VOTES_PER_B)     = v0;
        *(float4*)(outp + (size_t)i * VOTES_PER_B + 4) = v1;
    }
}

// ---------------------------------------------------------------------------
// Kernel B: full routing per sample. 1 CTA per b, 256 threads.
// SMEM: votes 22400 | pose 3200 | ra 175 | r 175 | agree 175 | a 8 | g 128 | b 128
// ---------------------------------------------------------------------------
#define SMEM_B_FLOATS (22400 + 3200 + 175 + 175 + 175 + 8 + 128 + 128)
#define SMEM_B_BYTES  (SMEM_B_FLOATS * 4)

__device__ __forceinline__ float warp_sum(float v) {
    #pragma unroll
    for (int o = 16; o; o >>= 1) v += __shfl_xor_sync(0xffffffffu, v, o);
    return v;
}
__device__ __forceinline__ float warp_max(float v) {
    #pragma unroll
    for (int o = 16; o; o >>= 1) v = fmaxf(v, __shfl_xor_sync(0xffffffffu, v, o));
    return v;
}

__device__ __forceinline__ void aggregate_ln(
    const float* __restrict__ sv, const float* __restrict__ sra,
    float* __restrict__ spose,
    const float* __restrict__ sg, const float* __restrict__ sb,
    int tid, int wrp, int lane)
{
    // pose_pre[k,m] = sum_n ra[n,k] * votes[n,k,m]
    for (int idx = tid; idx < KM; idx += 256) {
        const int k = idx >> 7, m = idx & 127;
        float s = 0.f;
        #pragma unroll
        for (int n = 0; n < N_IN; n++)
            s = fmaf(sra[n * K_CAPS + k], sv[(n * K_CAPS + k) * MC_DIM + m], s);
        spose[idx] = s;
    }
    __syncthreads();
    // LayerNorm over m per k, warp per k (in place)
    for (int k = wrp; k < K_CAPS; k += 8) {
        float v[4];
        float s = 0.f;
        #pragma unroll
        for (int j = 0; j < 4; j++) { v[j] = spose[k * MC_DIM + lane + 32 * j]; s += v[j]; }
        s = warp_sum(s);
        const float mu = s * (1.f / 128.f);
        float var = 0.f;
        #pragma unroll
        for (int j = 0; j < 4; j++) { float d = v[j] - mu; var += d * d; }
        var = warp_sum(var) * (1.f / 128.f);
        const float rs = rsqrtf(var + LN_EPS);
        #pragma unroll
        for (int j = 0; j < 4; j++) {
            const int m = lane + 32 * j;
            spose[k * MC_DIM + m] = (v[j] - mu) * rs * sg[m] + sb[m];
        }
    }
    __syncthreads();
}

__global__ __launch_bounds__(256) void routing_kernel(
    const float* __restrict__ acts_prior,
    const float* __restrict__ ln_gamma,
    const float* __restrict__ ln_beta,
    const float* __restrict__ cls_weight,
    const float* __restrict__ cls_bias,
    float* __restrict__ out)
{
    extern __shared__ float smem[];
    float* sv     = smem;                  // 22400
    float* spose  = sv + VOTES_PER_B;      // 3200
    float* sra    = spose + KM;            // 175
    float* sr     = sra + 175;             // 175
    float* sagree = sr + 175;              // 175
    float* sa     = sagree + 175;          // 8
    float* sg     = sa + 8;                // 128
    float* sb     = sg + 128;              // 128

    const int b   = blockIdx.x;
    const int tid = threadIdx.x;
    const int wrp = tid >> 5, lane = tid & 31;

    // stage votes + params
    {
        const float4* src = (const float4*)(g_votes + (size_t)b * VOTES_PER_B);
        float4* dst = (float4*)sv;
        for (int i = tid; i < VOTES_PER_B / 4; i += 256) dst[i] = src[i];
    }
    if (tid < N_IN) sa[tid] = acts_prior[b * N_IN + tid];
    if (tid < 128)  { sg[tid] = ln_gamma[tid]; sb[tid] = ln_beta[tid]; }
    // iter 0: uniform routing r = 1/25 -> ra = a/25
    if (tid < 175) sra[tid] = 0.f;  // placeholder, fixed after sa is loaded
    __syncthreads();
    if (tid < 175) sra[tid] = sa[tid / K_CAPS] * (1.f / 25.f);
    __syncthreads();

    aggregate_ln(sv, sra, spose, sg, sb, tid, wrp, lane);

    #pragma unroll 1
    for (int it = 1; it < 3; ++it) {
        // agree[n,k] = scale * sum_m votes[n,k,m]*pose[k,m]; warp per (n,k)
        for (int p = wrp; p < 175; p += 8) {
            const float* vp = sv + p * MC_DIM;
            const float* pp = spose + (p % K_CAPS) * MC_DIM;
            float d = 0.f;
            #pragma unroll
            for (int j = 0; j < 4; j++)
                d = fmaf(vp[lane + 32 * j], pp[lane + 32 * j], d);
            d = warp_sum(d);
            if (lane == 0) sagree[p] = d * AGREE_SCALE;
        }
        __syncthreads();
        // softmax over k per n: warps 0..6
        if (wrp < N_IN) {
            const float v = (lane < K_CAPS) ? sagree[wrp * K_CAPS + lane] : -1e30f;
            const float mx = warp_max(v);
            const float e = (lane < K_CAPS) ? expf(v - mx) : 0.f;
            const float s = warp_sum(e);
            if (lane < K_CAPS) {
                const float r = e / s;
                sr[wrp * K_CAPS + lane]  = r;
                sra[wrp * K_CAPS + lane] = r * sa[wrp];
            }
        }
        __syncthreads();
        aggregate_ln(sv, sra, spose, sg, sb, tid, wrp, lane);
    }

    // logits[k] = pose[k,:] . cls_weight[k,:] + bias[k]
    for (int k = wrp; k < K_CAPS; k += 8) {
        float d = 0.f;
        #pragma unroll
        for (int j = 0; j < 4; j++) {
            const int m = lane + 32 * j;
            d = fmaf(spose[k * MC_DIM + m], cls_weight[k * MC_DIM + m], d);
        }
        d = warp_sum(d);
        if (lane == 0) out[(size_t)b * K_CAPS + k] = d + cls_bias[k];
    }
    // final r
    if (tid < 175)
        out[(size_t)B_SZ * K_CAPS + (size_t)b * 175 + tid] = sr[tid];
}

// ---------------------------------------------------------------------------
extern "C" void kernel_launch(void* const* d_in, const int* in_sizes, int n_in,
                              void* d_out, int out_size)
{
    (void)in_sizes; (void)n_in; (void)out_size;
    const float* poses = (const float*)d_in[0];
    const float* acts  = (const float*)d_in[1];
    const float* w     = (const float*)d_in[2];
    const float* gamma = (const float*)d_in[3];
    const float* beta  = (const float*)d_in[4];
    const float* clsw  = (const float*)d_in[5];
    const float* clsb  = (const float*)d_in[6];
    float* out = (float*)d_out;

    votes_kernel<<<dim3(25, 32, 7), 256>>>(poses, w);

    cudaFuncSetAttribute(routing_kernel,
                         cudaFuncAttributeMaxDynamicSharedMemorySize,
                         SMEM_B_BYTES);
    routing_kernel<<<B_SZ, 256, SMEM_B_BYTES>>>(acts, gamma, beta, clsw, clsb, out);
}

// round 6
// speedup vs baseline: 1.7768x; 1.7768x over previous
#include <cuda_runtime.h>
#include <cuda_bf16.h>
#include <math.h>

// Problem constants
#define B_SZ    4096
#define N_IN    7
#define PC_DIM  256
#define K_CAPS  25
#define MC_DIM  128
#define KM      (K_CAPS * MC_DIM)      // 3200
#define VOTES_PER_B (N_IN * KM)        // 22400
#define POSE_STRIDE (N_IN * PC_DIM)    // 1792
#define LN_EPS  1e-5f
#define AGREE_SCALE 0.08838834764831845f   // 1/sqrt(128)

// scratch
__device__ float g_votes[(size_t)B_SZ * VOTES_PER_B];                 // 367 MB
__device__ __nv_bfloat16 g_pa_hi[(size_t)B_SZ * POSE_STRIDE];         // 14.7 MB
__device__ __nv_bfloat16 g_pa_lo[(size_t)B_SZ * POSE_STRIDE];
__device__ __nv_bfloat16 g_wb_hi[(size_t)N_IN * PC_DIM * KM];         // 11.5 MB (k-pair interleaved)
__device__ __nv_bfloat16 g_wb_lo[(size_t)N_IN * PC_DIM * KM];

// ---------------- helpers ----------------
__device__ __forceinline__ void mma_bf16(float& c0, float& c1, float& c2, float& c3,
                                         unsigned a0, unsigned a1, unsigned a2, unsigned a3,
                                         unsigned b0, unsigned b1) {
    asm volatile(
        "mma.sync.aligned.m16n8k16.row.col.f32.bf16.bf16.f32 "
        "{%0,%1,%2,%3}, {%4,%5,%6,%7}, {%8,%9}, {%0,%1,%2,%3};\n"
        : "+f"(c0), "+f"(c1), "+f"(c2), "+f"(c3)
        : "r"(a0), "r"(a1), "r"(a2), "r"(a3), "r"(b0), "r"(b1));
}
__device__ __forceinline__ void cp_async16(unsigned dst, const void* src) {
    asm volatile("cp.async.cg.shared.global [%0], [%1], 16;\n" :: "r"(dst), "l"(src));
}
__device__ __forceinline__ void cp_commit() { asm volatile("cp.async.commit_group;\n"); }
__device__ __forceinline__ void cp_wait0() { asm volatile("cp.async.wait_group 0;\n"); }
__device__ __forceinline__ void cp_wait1() { asm volatile("cp.async.wait_group 1;\n"); }

__device__ __forceinline__ float warp_sum(float v) {
    #pragma unroll
    for (int o = 16; o; o >>= 1) v += __shfl_xor_sync(0xffffffffu, v, o);
    return v;
}
__device__ __forceinline__ float warp_max(float v) {
    #pragma unroll
    for (int o = 16; o; o >>= 1) v = fmaxf(v, __shfl_xor_sync(0xffffffffu, v, o));
    return v;
}

// ---------------------------------------------------------------------------
// Decompose kernels: x -> bf16 hi + bf16 lo  (x = hi + lo to ~2^-18 rel)
// ---------------------------------------------------------------------------
__global__ __launch_bounds__(256) void decomp_poses_kernel(
    const float* __restrict__ poses,
    __nv_bfloat16* __restrict__ hi, __nv_bfloat16* __restrict__ lo)
{
    const int i = blockIdx.x * 256 + threadIdx.x;     // per 2 elems
    const int n2 = B_SZ * POSE_STRIDE / 2;
    if (i >= n2) return;
    const float2 x = ((const float2*)poses)[i];
    const __nv_bfloat16 h0 = __float2bfloat16(x.x);
    const __nv_bfloat16 h1 = __float2bfloat16(x.y);
    const __nv_bfloat16 l0 = __float2bfloat16(x.x - __bfloat162float(h0));
    const __nv_bfloat16 l1 = __float2bfloat16(x.y - __bfloat162float(h1));
    ((__nv_bfloat162*)hi)[i] = __nv_bfloat162(h0, h1);
    ((__nv_bfloat162*)lo)[i] = __nv_bfloat162(l0, l1);
}

// w[n][d][km] -> wb[n][dp][km][par], par = d&1, dp = d>>1  (k-pair interleave)
__global__ __launch_bounds__(256) void decomp_w_kernel(
    const float* __restrict__ w,
    __nv_bfloat16* __restrict__ hi, __nv_bfloat16* __restrict__ lo)
{
    const int i = blockIdx.x * 256 + threadIdx.x;     // (n, dp, km)
    const int tot = N_IN * (PC_DIM / 2) * KM;
    if (i >= tot) return;
    const int km = i % KM;
    const int dp = (i / KM) % (PC_DIM / 2);
    const int n  = i / (KM * (PC_DIM / 2));
    const float x0 = w[((size_t)(n * PC_DIM + 2 * dp))     * KM + km];
    const float x1 = w[((size_t)(n * PC_DIM + 2 * dp + 1)) * KM + km];
    const __nv_bfloat16 h0 = __float2bfloat16(x0);
    const __nv_bfloat16 h1 = __float2bfloat16(x1);
    const __nv_bfloat16 l0 = __float2bfloat16(x0 - __bfloat162float(h0));
    const __nv_bfloat16 l1 = __float2bfloat16(x1 - __bfloat162float(h1));
    ((__nv_bfloat162*)hi)[i] = __nv_bfloat162(h0, h1);
    ((__nv_bfloat162*)lo)[i] = __nv_bfloat162(l0, l1);
}

// ---------------------------------------------------------------------------
// Kernel A: bf16 3-term split GEMM on tensor cores.
//   votes = A_hi*B_hi + A_hi*B_lo + A_lo*B_hi   (fp32 accum)
// 7 GEMMs [4096,256]@[256,3200], tile 128x128, BK=32, 3 phases -> 24 stages.
// 256 threads, warp grid 2(M)x4(N), warp tile 64x32, mma m16n8k16 bf16.
// ---------------------------------------------------------------------------
#define APITCH 40                       // bf16 per A smem row (pad)
#define BPITCH 272                      // bf16 per B smem row (128*2 + 16 pad)
#define A_BUF_H (128 * APITCH)          // 5120 bf16
#define B_BUF_H (16 * BPITCH)           // 4352 bf16

__global__ __launch_bounds__(256, 2) void votes_bf16x3_kernel(
    const __nv_bfloat16* __restrict__ pa_hi,
    const __nv_bfloat16* __restrict__ pa_lo,
    const __nv_bfloat16* __restrict__ wb_hi,
    const __nv_bfloat16* __restrict__ wb_lo)
{
    const int n  = blockIdx.z;
    const int tm = blockIdx.y;   // b tile (0..31)
    const int tn = blockIdx.x;   // km tile (0..24)

    __shared__ __nv_bfloat16 sA[2][A_BUF_H];
    __shared__ __nv_bfloat16 sB[2][B_BUF_H];

    const int tid  = threadIdx.x;
    const int lane = tid & 31;
    const int wrp  = tid >> 5;
    const int wm   = wrp >> 2;        // 0..1
    const int wn   = wrp & 3;         // 0..3
    const int grp  = lane >> 2;       // 0..7
    const int tig  = lane & 3;        // 0..3

    // A tile base (elem offsets in bf16 units)
    const size_t a_off = (size_t)(tm * 128) * POSE_STRIDE + n * PC_DIM;
    // B tile base: wb[n][dp][km][2]; row dp stride 6400 bf16, col tn*128 km -> *2
    const size_t b_off = (size_t)(n * (PC_DIM / 2)) * (KM * 2) + tn * 128 * 2;

    const __nv_bfloat16* Abases[3] = { pa_hi + a_off, pa_hi + a_off, pa_lo + a_off };
    const __nv_bfloat16* Bbases[3] = { wb_hi + b_off, wb_lo + b_off, wb_hi + b_off };

    const unsigned sA_u = (unsigned)__cvta_generic_to_shared(&sA[0][0]);
    const unsigned sB_u = (unsigned)__cvta_generic_to_shared(&sB[0][0]);

    auto stage = [&](int buf, int t) {
        const int ph = t >> 3;          // phase 0..2
        const int kb = t & 7;           // 0..7
        const __nv_bfloat16* Ab = Abases[ph];
        const __nv_bfloat16* Bb = Bbases[ph];
        // A: 128 rows x 32 bf16; 4 cp16 per row; 512 cp16
        #pragma unroll
        for (int i = 0; i < 2; i++) {
            const int idx = tid + 256 * i;
            const int m = idx >> 2, seg = idx & 3;
            cp_async16(sA_u + (buf * A_BUF_H + m * APITCH + seg * 8) * 2,
                       Ab + (size_t)m * POSE_STRIDE + kb * 32 + seg * 8);
        }
        // B: 16 dp rows x 256 bf16; 32 cp16 per row; 512 cp16
        #pragma unroll
        for (int i = 0; i < 2; i++) {
            const int idx = tid + 256 * i;
            const int dp = idx >> 5, seg = idx & 31;
            cp_async16(sB_u + (buf * B_BUF_H + dp * BPITCH + seg * 8) * 2,
                       Bb + (size_t)(kb * 16 + dp) * (KM * 2) + seg * 8);
        }
        cp_commit();
    };

    float acc[4][4][4];
    #pragma unroll
    for (int mi = 0; mi < 4; mi++)
        #pragma unroll
        for (int ni = 0; ni < 4; ni++)
            #pragma unroll
            for (int c = 0; c < 4; c++) acc[mi][ni][c] = 0.f;

    stage(0, 0);

    #pragma unroll 1
    for (int t = 0; t < 24; ++t) {
        if (t < 23) stage((t + 1) & 1, t + 1);
        if (t < 23) cp_wait1(); else cp_wait0();
        __syncthreads();

        const __nv_bfloat16* pA = &sA[t & 1][0];
        const __nv_bfloat16* pB = &sB[t & 1][0];

        #pragma unroll
        for (int ks = 0; ks < 2; ++ks) {
            // A fragments
            unsigned af[4][4];
            #pragma unroll
            for (int mi = 0; mi < 4; mi++) {
                const int rb = wm * 64 + mi * 16;
                const int kc = ks * 16 + 2 * tig;
                af[mi][0] = *(const unsigned*)&pA[(rb + grp)     * APITCH + kc];
                af[mi][1] = *(const unsigned*)&pA[(rb + grp + 8) * APITCH + kc];
                af[mi][2] = *(const unsigned*)&pA[(rb + grp)     * APITCH + kc + 8];
                af[mi][3] = *(const unsigned*)&pA[(rb + grp + 8) * APITCH + kc + 8];
            }
            // B fragments (k-pair interleaved rows)
            unsigned bf[4][2];
            #pragma unroll
            for (int ni = 0; ni < 4; ni++) {
                const int col = wn * 32 + ni * 8 + grp;
                bf[ni][0] = *(const unsigned*)&pB[(ks * 8 + tig)     * BPITCH + col * 2];
                bf[ni][1] = *(const unsigned*)&pB[(ks * 8 + tig + 4) * BPITCH + col * 2];
            }
            #pragma unroll
            for (int mi = 0; mi < 4; mi++)
                #pragma unroll
                for (int ni = 0; ni < 4; ni++)
                    mma_bf16(acc[mi][ni][0], acc[mi][ni][1], acc[mi][ni][2], acc[mi][ni][3],
                             af[mi][0], af[mi][1], af[mi][2], af[mi][3],
                             bf[ni][0], bf[ni][1]);
        }
        __syncthreads();
    }

    // epilogue
    #pragma unroll
    for (int mi = 0; mi < 4; mi++) {
        const int row = tm * 128 + wm * 64 + mi * 16 + grp;
        #pragma unroll
        for (int ni = 0; ni < 4; ni++) {
            const int col = tn * 128 + wn * 32 + ni * 8 + 2 * tig;
            float* p0 = g_votes + (size_t)row * VOTES_PER_B + n * KM + col;
            float* p1 = g_votes + (size_t)(row + 8) * VOTES_PER_B + n * KM + col;
            *(float2*)p0 = make_float2(acc[mi][ni][0], acc[mi][ni][1]);
            *(float2*)p1 = make_float2(acc[mi][ni][2], acc[mi][ni][3]);
        }
    }
}

// ---------------------------------------------------------------------------
// Kernel B: routing. 147 CTAs x 512 threads, 28 samples each,
// double-buffered cp.async votes staging, float4 LDS everywhere.
// All smem sub-arrays padded to multiples of 4 floats (16B alignment).
// ---------------------------------------------------------------------------
#define SPB 28
#define RT_GRID 147
// sv 2*22400 | spose 3200 | sra 176 | sr 176 | sagree 176 | sa 8 | sg 128 | sb 128
#define SMEM_RT_FLOATS (2*VOTES_PER_B + KM + 176 + 176 + 176 + 8 + 128 + 128)
#define SMEM_RT_BYTES  (SMEM_RT_FLOATS * 4)

__global__ __launch_bounds__(512, 1) void routing_kernel(
    const float* __restrict__ acts_prior,
    const float* __restrict__ ln_gamma,
    const float* __restrict__ ln_beta,
    const float* __restrict__ cls_weight,
    const float* __restrict__ cls_bias,
    float* __restrict__ out)
{
    extern __shared__ float smem[];
    float* sv     = smem;                      // 2 x 22400
    float* spose  = sv + 2 * VOTES_PER_B;      // 3200
    float* sra    = spose + KM;                // 176 (175 used)
    float* sr     = sra + 176;                 // 176 (175 used)
    float* sagree = sr + 176;                  // 176 (175 used)
    float* sa     = sagree + 176;              // 8
    float* sg     = sa + 8;                    // 128  (16B-aligned base)
    float* sb     = sg + 128;                  // 128  (16B-aligned base)

    const int tid  = threadIdx.x;
    const int wrp  = tid >> 5, lane = tid & 31;
    const int b0   = blockIdx.x * SPB;
    const int nb   = min(SPB, B_SZ - b0);

    const unsigned sv_u = (unsigned)__cvta_generic_to_shared(sv);

    auto stage = [&](int buf, int b) {
        const float* src = g_votes + (size_t)b * VOTES_PER_B;
        const unsigned base = sv_u + (unsigned)buf * VOTES_PER_B * 4;
        #pragma unroll
        for (int i = 0; i < 11; i++) {
            const int idx = tid + i * 512;
            if (idx < VOTES_PER_B / 4)
                cp_async16(base + idx * 16, src + idx * 4);
        }
        cp_commit();
    };

    if (tid < 128) { sg[tid] = ln_gamma[tid]; sb[tid] = ln_beta[tid]; }

    stage(0, b0);

    #pragma unroll 1
    for (int s = 0; s < nb; ++s) {
        const int b = b0 + s;
        if (s + 1 < nb) stage((s + 1) & 1, b + 1);
        if (tid < N_IN) sa[tid] = acts_prior[(size_t)b * N_IN + tid];
        if (s + 1 < nb) cp_wait1(); else cp_wait0();
        __syncthreads();

        const float* v = sv + (s & 1) * VOTES_PER_B;

        // iter 0: ra = a/25
        if (tid < 175) sra[tid] = sa[tid / K_CAPS] * (1.f / 25.f);
        __syncthreads();

        #pragma unroll 1
        for (int it = 0; it < 3; ++it) {
            if (it > 0) {
                // agree[n,k] = scale * <votes[n,k,:], pose[k,:]>, warp per (n,k)
                for (int p = wrp; p < 175; p += 16) {
                    const float4 vv = *(const float4*)&v[(p << 7) + lane * 4];
                    const float4 pp = *(const float4*)&spose[((p % K_CAPS) << 7) + lane * 4];
                    float d = vv.x * pp.x + vv.y * pp.y + vv.z * pp.z + vv.w * pp.w;
                    d = warp_sum(d);
                    if (lane == 0) sagree[p] = d * AGREE_SCALE;
                }
                __syncthreads();
                // softmax over k per n (warps 0..6)
                if (wrp < N_IN) {
                    const float x = (lane < K_CAPS) ? sagree[wrp * K_CAPS + lane] : -1e30f;
                    const float mx = warp_max(x);
                    const float e = (lane < K_CAPS) ? __expf(x - mx) : 0.f;
                    const float ssum = warp_sum(e);
                    if (lane < K_CAPS) {
                        const float r = e / ssum;
                        sr[wrp * K_CAPS + lane]  = r;
                        sra[wrp * K_CAPS + lane] = r * sa[wrp];
                    }
                }
                __syncthreads();
            }
            // aggregate: pose_pre[k,m] = sum_n ra[n,k]*votes[n,k,m], float4 per thread
            for (int p = tid; p < 800; p += 512) {
                const int k = p >> 5, m4 = (p & 31) << 2;
                float4 acc = make_float4(0.f, 0.f, 0.f, 0.f);
                #pragma unroll
                for (int nn = 0; nn < N_IN; nn++) {
                    const float rr = sra[nn * K_CAPS + k];
                    const float4 vv = *(const float4*)&v[((nn * K_CAPS + k) << 7) + m4];
                    acc.x = fmaf(rr, vv.x, acc.x);
                    acc.y = fmaf(rr, vv.y, acc.y);
                    acc.z = fmaf(rr, vv.z, acc.z);
                    acc.w = fmaf(rr, vv.w, acc.w);
                }
                *(float4*)&spose[(k << 7) + m4] = acc;
            }
            __syncthreads();
            // LayerNorm per k (warp per k), in place
            for (int k = wrp; k < K_CAPS; k += 16) {
                float4 x = *(const float4*)&spose[(k << 7) + lane * 4];
                float ssum = x.x + x.y + x.z + x.w;
                ssum = warp_sum(ssum);
                const float mu = ssum * (1.f / 128.f);
                float var = (x.x - mu) * (x.x - mu) + (x.y - mu) * (x.y - mu)
                          + (x.z - mu) * (x.z - mu) + (x.w - mu) * (x.w - mu);
                var = warp_sum(var) * (1.f / 128.f);
                const float rs = rsqrtf(var + LN_EPS);
                const float4 g4 = *(const float4*)&sg[lane * 4];
                const float4 b4 = *(const float4*)&sb[lane * 4];
                float4 o;
                o.x = (x.x - mu) * rs * g4.x + b4.x;
                o.y = (x.y - mu) * rs * g4.y + b4.y;
                o.z = (x.z - mu) * rs * g4.z + b4.z;
                o.w = (x.w - mu) * rs * g4.w + b4.w;
                *(float4*)&spose[(k << 7) + lane * 4] = o;
            }
            __syncthreads();
        }

        // logits
        for (int k = wrp; k < K_CAPS; k += 16) {
            const float4 pp = *(const float4*)&spose[(k << 7) + lane * 4];
            const float4 cw = *(const float4*)&cls_weight[(k << 7) + lane * 4];
            float d = pp.x * cw.x + pp.y * cw.y + pp.z * cw.z + pp.w * cw.w;
            d = warp_sum(d);
            if (lane == 0) out[(size_t)b * K_CAPS + k] = d + cls_bias[k];
        }
        // final r
        if (tid < 175)
            out[(size_t)B_SZ * K_CAPS + (size_t)b * 175 + tid] = sr[tid];
        __syncthreads();
    }
}

// ---------------------------------------------------------------------------
extern "C" void kernel_launch(void* const* d_in, const int* in_sizes, int n_in,
                              void* d_out, int out_size)
{
    (void)in_sizes; (void)n_in; (void)out_size;
    const float* poses = (const float*)d_in[0];
    const float* acts  = (const float*)d_in[1];
    const float* w     = (const float*)d_in[2];
    const float* gamma = (const float*)d_in[3];
    const float* beta  = (const float*)d_in[4];
    const float* clsw  = (const float*)d_in[5];
    const float* clsb  = (const float*)d_in[6];
    float* out = (float*)d_out;

    __nv_bfloat16 *pa_hi, *pa_lo, *wb_hi, *wb_lo;
    cudaGetSymbolAddress((void**)&pa_hi, g_pa_hi);
    cudaGetSymbolAddress((void**)&pa_lo, g_pa_lo);
    cudaGetSymbolAddress((void**)&wb_hi, g_wb_hi);
    cudaGetSymbolAddress((void**)&wb_lo, g_wb_lo);

    {
        const int n2 = B_SZ * POSE_STRIDE / 2;
        decomp_poses_kernel<<<(n2 + 255) / 256, 256>>>(poses, pa_hi, pa_lo);
        const int tot = N_IN * (PC_DIM / 2) * KM;
        decomp_w_kernel<<<(tot + 255) / 256, 256>>>(w, wb_hi, wb_lo);
    }

    votes_bf16x3_kernel<<<dim3(25, 32, 7), 256>>>(pa_hi, pa_lo, wb_hi, wb_lo);

    cudaFuncSetAttribute(routing_kernel,
                         cudaFuncAttributeMaxDynamicSharedMemorySize,
                         SMEM_RT_BYTES);
    routing_kernel<<<RT_GRID, 512, SMEM_RT_BYTES>>>(acts, gamma, beta, clsw, clsb, out);
}

// round 7
// speedup vs baseline: 2.1770x; 1.2253x over previous
#include <cuda_runtime.h>
#include <cuda_bf16.h>
#include <math.h>

// Problem constants
#define B_SZ    4096
#define N_IN    7
#define PC_DIM  256
#define K_CAPS  25
#define MC_DIM  128
#define KM      (K_CAPS * MC_DIM)      // 3200
#define VOTES_PER_B (N_IN * KM)        // 22400
#define POSE_STRIDE (N_IN * PC_DIM)    // 1792
#define LN_EPS  1e-5f
#define AGREE_SCALE 0.08838834764831845f   // 1/sqrt(128)

// scratch
__device__ float g_votes[(size_t)B_SZ * VOTES_PER_B];                 // 367 MB
__device__ __nv_bfloat16 g_pa_hi[(size_t)B_SZ * POSE_STRIDE];         // 14.7 MB
__device__ __nv_bfloat16 g_pa_lo[(size_t)B_SZ * POSE_STRIDE];
__device__ __nv_bfloat16 g_wb_hi[(size_t)N_IN * PC_DIM * KM];         // 11.5 MB (k-pair interleaved)
__device__ __nv_bfloat16 g_wb_lo[(size_t)N_IN * PC_DIM * KM];

// ---------------- helpers ----------------
__device__ __forceinline__ void mma_bf16(float& c0, float& c1, float& c2, float& c3,
                                         unsigned a0, unsigned a1, unsigned a2, unsigned a3,
                                         unsigned b0, unsigned b1) {
    asm volatile(
        "mma.sync.aligned.m16n8k16.row.col.f32.bf16.bf16.f32 "
        "{%0,%1,%2,%3}, {%4,%5,%6,%7}, {%8,%9}, {%0,%1,%2,%3};\n"
        : "+f"(c0), "+f"(c1), "+f"(c2), "+f"(c3)
        : "r"(a0), "r"(a1), "r"(a2), "r"(a3), "r"(b0), "r"(b1));
}
__device__ __forceinline__ void cp_async16(unsigned dst, const void* src) {
    asm volatile("cp.async.cg.shared.global [%0], [%1], 16;\n" :: "r"(dst), "l"(src));
}
__device__ __forceinline__ void cp_commit() { asm volatile("cp.async.commit_group;\n"); }
__device__ __forceinline__ void cp_wait0() { asm volatile("cp.async.wait_group 0;\n"); }
__device__ __forceinline__ void cp_wait1() { asm volatile("cp.async.wait_group 1;\n"); }

__device__ __forceinline__ float warp_sum(float v) {
    #pragma unroll
    for (int o = 16; o; o >>= 1) v += __shfl_xor_sync(0xffffffffu, v, o);
    return v;
}
__device__ __forceinline__ float warp_max(float v) {
    #pragma unroll
    for (int o = 16; o; o >>= 1) v = fmaxf(v, __shfl_xor_sync(0xffffffffu, v, o));
    return v;
}

// ---------------------------------------------------------------------------
// Decompose kernels: x -> bf16 hi + bf16 lo  (x = hi + lo to ~2^-18 rel)
// ---------------------------------------------------------------------------
__global__ __launch_bounds__(256) void decomp_poses_kernel(
    const float* __restrict__ poses,
    __nv_bfloat16* __restrict__ hi, __nv_bfloat16* __restrict__ lo)
{
    const int i = blockIdx.x * 256 + threadIdx.x;     // per 2 elems
    const int n2 = B_SZ * POSE_STRIDE / 2;
    if (i >= n2) return;
    const float2 x = ((const float2*)poses)[i];
    const __nv_bfloat16 h0 = __float2bfloat16(x.x);
    const __nv_bfloat16 h1 = __float2bfloat16(x.y);
    const __nv_bfloat16 l0 = __float2bfloat16(x.x - __bfloat162float(h0));
    const __nv_bfloat16 l1 = __float2bfloat16(x.y - __bfloat162float(h1));
    ((__nv_bfloat162*)hi)[i] = __nv_bfloat162(h0, h1);
    ((__nv_bfloat162*)lo)[i] = __nv_bfloat162(l0, l1);
}

// w[n][d][km] -> wb[n][dp][km][par], par = d&1, dp = d>>1  (k-pair interleave)
__global__ __launch_bounds__(256) void decomp_w_kernel(
    const float* __restrict__ w,
    __nv_bfloat16* __restrict__ hi, __nv_bfloat16* __restrict__ lo)
{
    const int i = blockIdx.x * 256 + threadIdx.x;     // (n, dp, km)
    const int tot = N_IN * (PC_DIM / 2) * KM;
    if (i >= tot) return;
    const int km = i % KM;
    const int dp = (i / KM) % (PC_DIM / 2);
    const int n  = i / (KM * (PC_DIM / 2));
    const float x0 = w[((size_t)(n * PC_DIM + 2 * dp))     * KM + km];
    const float x1 = w[((size_t)(n * PC_DIM + 2 * dp + 1)) * KM + km];
    const __nv_bfloat16 h0 = __float2bfloat16(x0);
    const __nv_bfloat16 h1 = __float2bfloat16(x1);
    const __nv_bfloat16 l0 = __float2bfloat16(x0 - __bfloat162float(h0));
    const __nv_bfloat16 l1 = __float2bfloat16(x1 - __bfloat162float(h1));
    ((__nv_bfloat162*)hi)[i] = __nv_bfloat162(h0, h1);
    ((__nv_bfloat162*)lo)[i] = __nv_bfloat162(l0, l1);
}

// ---------------------------------------------------------------------------
// Kernel A: bf16 3-term split GEMM on tensor cores.
//   votes = A_hi*B_hi + A_hi*B_lo + A_lo*B_hi   (fp32 accum)
// 7 GEMMs [4096,256]@[256,3200], tile 128x128, BK=32, 3 phases -> 24 stages.
// 256 threads, warp grid 2(M)x4(N), warp tile 64x32, mma m16n8k16 bf16.
// ---------------------------------------------------------------------------
#define APITCH 40                       // bf16 per A smem row (pad)
#define BPITCH 272                      // bf16 per B smem row (128*2 + 16 pad)
#define A_BUF_H (128 * APITCH)          // 5120 bf16
#define B_BUF_H (16 * BPITCH)           // 4352 bf16

__global__ __launch_bounds__(256, 2) void votes_bf16x3_kernel(
    const __nv_bfloat16* __restrict__ pa_hi,
    const __nv_bfloat16* __restrict__ pa_lo,
    const __nv_bfloat16* __restrict__ wb_hi,
    const __nv_bfloat16* __restrict__ wb_lo)
{
    const int n  = blockIdx.z;
    const int tm = blockIdx.y;   // b tile (0..31)
    const int tn = blockIdx.x;   // km tile (0..24)

    __shared__ __nv_bfloat16 sA[2][A_BUF_H];
    __shared__ __nv_bfloat16 sB[2][B_BUF_H];

    const int tid  = threadIdx.x;
    const int lane = tid & 31;
    const int wrp  = tid >> 5;
    const int wm   = wrp >> 2;        // 0..1
    const int wn   = wrp & 3;         // 0..3
    const int grp  = lane >> 2;       // 0..7
    const int tig  = lane & 3;        // 0..3

    // A tile base (elem offsets in bf16 units)
    const size_t a_off = (size_t)(tm * 128) * POSE_STRIDE + n * PC_DIM;
    // B tile base: wb[n][dp][km][2]; row dp stride 6400 bf16, col tn*128 km -> *2
    const size_t b_off = (size_t)(n * (PC_DIM / 2)) * (KM * 2) + tn * 128 * 2;

    const __nv_bfloat16* Abases[3] = { pa_hi + a_off, pa_hi + a_off, pa_lo + a_off };
    const __nv_bfloat16* Bbases[3] = { wb_hi + b_off, wb_lo + b_off, wb_hi + b_off };

    const unsigned sA_u = (unsigned)__cvta_generic_to_shared(&sA[0][0]);
    const unsigned sB_u = (unsigned)__cvta_generic_to_shared(&sB[0][0]);

    auto stage = [&](int buf, int t) {
        const int ph = t >> 3;          // phase 0..2
        const int kb = t & 7;           // 0..7
        const __nv_bfloat16* Ab = Abases[ph];
        const __nv_bfloat16* Bb = Bbases[ph];
        // A: 128 rows x 32 bf16; 4 cp16 per row; 512 cp16
        #pragma unroll
        for (int i = 0; i < 2; i++) {
            const int idx = tid + 256 * i;
            const int m = idx >> 2, seg = idx & 3;
            cp_async16(sA_u + (buf * A_BUF_H + m * APITCH + seg * 8) * 2,
                       Ab + (size_t)m * POSE_STRIDE + kb * 32 + seg * 8);
        }
        // B: 16 dp rows x 256 bf16; 32 cp16 per row; 512 cp16
        #pragma unroll
        for (int i = 0; i < 2; i++) {
            const int idx = tid + 256 * i;
            const int dp = idx >> 5, seg = idx & 31;
            cp_async16(sB_u + (buf * B_BUF_H + dp * BPITCH + seg * 8) * 2,
                       Bb + (size_t)(kb * 16 + dp) * (KM * 2) + seg * 8);
        }
        cp_commit();
    };

    float acc[4][4][4];
    #pragma unroll
    for (int mi = 0; mi < 4; mi++)
        #pragma unroll
        for (int ni = 0; ni < 4; ni++)
            #pragma unroll
            for (int c = 0; c < 4; c++) acc[mi][ni][c] = 0.f;

    stage(0, 0);

    #pragma unroll 1
    for (int t = 0; t < 24; ++t) {
        if (t < 23) stage((t + 1) & 1, t + 1);
        if (t < 23) cp_wait1(); else cp_wait0();
        __syncthreads();

        const __nv_bfloat16* pA = &sA[t & 1][0];
        const __nv_bfloat16* pB = &sB[t & 1][0];

        #pragma unroll
        for (int ks = 0; ks < 2; ++ks) {
            // A fragments
            unsigned af[4][4];
            #pragma unroll
            for (int mi = 0; mi < 4; mi++) {
                const int rb = wm * 64 + mi * 16;
                const int kc = ks * 16 + 2 * tig;
                af[mi][0] = *(const unsigned*)&pA[(rb + grp)     * APITCH + kc];
                af[mi][1] = *(const unsigned*)&pA[(rb + grp + 8) * APITCH + kc];
                af[mi][2] = *(const unsigned*)&pA[(rb + grp)     * APITCH + kc + 8];
                af[mi][3] = *(const unsigned*)&pA[(rb + grp + 8) * APITCH + kc + 8];
            }
            // B fragments (k-pair interleaved rows)
            unsigned bf[4][2];
            #pragma unroll
            for (int ni = 0; ni < 4; ni++) {
                const int col = wn * 32 + ni * 8 + grp;
                bf[ni][0] = *(const unsigned*)&pB[(ks * 8 + tig)     * BPITCH + col * 2];
                bf[ni][1] = *(const unsigned*)&pB[(ks * 8 + tig + 4) * BPITCH + col * 2];
            }
            #pragma unroll
            for (int mi = 0; mi < 4; mi++)
                #pragma unroll
                for (int ni = 0; ni < 4; ni++)
                    mma_bf16(acc[mi][ni][0], acc[mi][ni][1], acc[mi][ni][2], acc[mi][ni][3],
                             af[mi][0], af[mi][1], af[mi][2], af[mi][3],
                             bf[ni][0], bf[ni][1]);
        }
        __syncthreads();
    }

    // epilogue
    #pragma unroll
    for (int mi = 0; mi < 4; mi++) {
        const int row = tm * 128 + wm * 64 + mi * 16 + grp;
        #pragma unroll
        for (int ni = 0; ni < 4; ni++) {
            const int col = tn * 128 + wn * 32 + ni * 8 + 2 * tig;
            float* p0 = g_votes + (size_t)row * VOTES_PER_B + n * KM + col;
            float* p1 = g_votes + (size_t)(row + 8) * VOTES_PER_B + n * KM + col;
            *(float2*)p0 = make_float2(acc[mi][ni][0], acc[mi][ni][1]);
            *(float2*)p1 = make_float2(acc[mi][ni][2], acc[mi][ni][3]);
        }
    }
}

// ---------------------------------------------------------------------------
// Kernel B: register-resident routing. 148 CTAs x 800 threads (25 warps).
// Warp w owns capsule k=w; lane owns m in [4*lane, 4*lane+4).
// Votes loaded once per sample directly from GMEM into registers.
// ---------------------------------------------------------------------------
#define RT_GRID 148

__global__ __launch_bounds__(800, 1) void routing_kernel(
    const float* __restrict__ acts_prior,
    const float* __restrict__ ln_gamma,
    const float* __restrict__ ln_beta,
    const float* __restrict__ cls_weight,
    const float* __restrict__ cls_bias,
    float* __restrict__ out)
{
    __shared__ float sa[8];
    __shared__ float sagree[184];
    __shared__ float sra[184];

    const int tid  = threadIdx.x;
    const int wrp  = tid >> 5;        // = k, 0..24
    const int lane = tid & 31;
    const int k    = wrp;

    // constants (per-thread, fixed across samples)
    const float4 g4  = *(const float4*)&ln_gamma[lane * 4];
    const float4 b4  = *(const float4*)&ln_beta[lane * 4];
    const float4 cw4 = *(const float4*)&cls_weight[k * MC_DIM + lane * 4];
    const float  bias = cls_bias[k];

    #pragma unroll 1
    for (int b = blockIdx.x; b < B_SZ; b += RT_GRID) {
        if (tid < N_IN) sa[tid] = acts_prior[(size_t)b * N_IN + tid];

        // load this warp's votes slice: v[n] = votes[b][n][k][4*lane .. +4)
        float4 v[N_IN];
        {
            const float* vb = g_votes + (size_t)b * VOTES_PER_B + k * MC_DIM + lane * 4;
            #pragma unroll
            for (int n = 0; n < N_IN; n++)
                v[n] = *(const float4*)(vb + n * KM);
        }
        __syncthreads();   // sa visible

        // iter 0: ra = a/25
        float ra[N_IN];
        #pragma unroll
        for (int n = 0; n < N_IN; n++) ra[n] = sa[n] * (1.f / 25.f);

        float4 pose;
        #pragma unroll 1
        for (int it = 0; it < 3; ++it) {
            if (it > 0) {
                // agree[n] = scale * <v[n], pose> (warp reduction over m)
                #pragma unroll
                for (int n = 0; n < N_IN; n++) {
                    float d = v[n].x * pose.x + v[n].y * pose.y
                            + v[n].z * pose.z + v[n].w * pose.w;
                    d = warp_sum(d);
                    if (lane == 0) sagree[n * K_CAPS + k] = d * AGREE_SCALE;
                }
                __syncthreads();
                // softmax over k per n: warps 0..6
                if (wrp < N_IN) {
                    const float x = (lane < K_CAPS) ? sagree[wrp * K_CAPS + lane] : -1e30f;
                    const float mx = warp_max(x);
                    const float e = (lane < K_CAPS) ? __expf(x - mx) : 0.f;
                    const float ssum = warp_sum(e);
                    if (lane < K_CAPS) {
                        const float r = e / ssum;
                        sra[wrp * K_CAPS + lane] = r * sa[wrp];
                        if (it == 2)
                            out[(size_t)B_SZ * K_CAPS + (size_t)b * 175
                                + wrp * K_CAPS + lane] = r;
                    }
                }
                __syncthreads();
                #pragma unroll
                for (int n = 0; n < N_IN; n++) ra[n] = sra[n * K_CAPS + k];
            }
            // aggregate: pose = sum_n ra[n] * v[n]  (registers only)
            pose = make_float4(0.f, 0.f, 0.f, 0.f);
            #pragma unroll
            for (int n = 0; n < N_IN; n++) {
                pose.x = fmaf(ra[n], v[n].x, pose.x);
                pose.y = fmaf(ra[n], v[n].y, pose.y);
                pose.z = fmaf(ra[n], v[n].z, pose.z);
                pose.w = fmaf(ra[n], v[n].w, pose.w);
            }
            // LayerNorm over m (warp reduction)
            {
                float s = pose.x + pose.y + pose.z + pose.w;
                s = warp_sum(s);
                const float mu = s * (1.f / 128.f);
                float var = (pose.x - mu) * (pose.x - mu) + (pose.y - mu) * (pose.y - mu)
                          + (pose.z - mu) * (pose.z - mu) + (pose.w - mu) * (pose.w - mu);
                var = warp_sum(var) * (1.f / 128.f);
                const float rs = rsqrtf(var + LN_EPS);
                pose.x = (pose.x - mu) * rs * g4.x + b4.x;
                pose.y = (pose.y - mu) * rs * g4.y + b4.y;
                pose.z = (pose.z - mu) * rs * g4.z + b4.z;
                pose.w = (pose.w - mu) * rs * g4.w + b4.w;
            }
        }

        // logits[k] = <pose, cls_weight[k]> + bias
        {
            float d = pose.x * cw4.x + pose.y * cw4.y + pose.z * cw4.z + pose.w * cw4.w;
            d = warp_sum(d);
            if (lane == 0) out[(size_t)b * K_CAPS + k] = d + bias;
        }
    }
}

// ---------------------------------------------------------------------------
extern "C" void kernel_launch(void* const* d_in, const int* in_sizes, int n_in,
                              void* d_out, int out_size)
{
    (void)in_sizes; (void)n_in; (void)out_size;
    const float* poses = (const float*)d_in[0];
    const float* acts  = (const float*)d_in[1];
    const float* w     = (const float*)d_in[2];
    const float* gamma = (const float*)d_in[3];
    const float* beta  = (const float*)d_in[4];
    const float* clsw  = (const float*)d_in[5];
    const float* clsb  = (const float*)d_in[6];
    float* out = (float*)d_out;

    __nv_bfloat16 *pa_hi, *pa_lo, *wb_hi, *wb_lo;
    cudaGetSymbolAddress((void**)&pa_hi, g_pa_hi);
    cudaGetSymbolAddress((void**)&pa_lo, g_pa_lo);
    cudaGetSymbolAddress((void**)&wb_hi, g_wb_hi);
    cudaGetSymbolAddress((void**)&wb_lo, g_wb_lo);

    {
        const int n2 = B_SZ * POSE_STRIDE / 2;
        decomp_poses_kernel<<<(n2 + 255) / 256, 256>>>(poses, pa_hi, pa_lo);
        const int tot = N_IN * (PC_DIM / 2) * KM;
        decomp_w_kernel<<<(tot + 255) / 256, 256>>>(w, wb_hi, wb_lo);
    }

    votes_bf16x3_kernel<<<dim3(25, 32, 7), 256>>>(pa_hi, pa_lo, wb_hi, wb_lo);

    routing_kernel<<<RT_GRID, 800>>>(acts, gamma, beta, clsw, clsb, out);
}

// round 9
// speedup vs baseline: 2.5768x; 1.1836x over previous
#include <cuda_runtime.h>
#include <cuda_bf16.h>
#include <math.h>
#include <stdint.h>

// Problem constants
#define B_SZ    4096
#define N_IN    7
#define PC_DIM  256
#define K_CAPS  25
#define MC_DIM  128
#define KM      (K_CAPS * MC_DIM)      // 3200
#define VOTES_PER_B (N_IN * KM)        // 22400
#define POSE_STRIDE (N_IN * PC_DIM)    // 1792
#define LN_EPS  1e-5f
#define AGREE_SCALE 0.08838834764831845f   // 1/sqrt(128)

// scratch
__device__ float g_votes[(size_t)B_SZ * VOTES_PER_B];                 // 367 MB
__device__ __nv_bfloat16 g_pa_hi[(size_t)B_SZ * POSE_STRIDE];         // 14.7 MB
__device__ __nv_bfloat16 g_pa_lo[(size_t)B_SZ * POSE_STRIDE];
// transposed weights: wt[n][km][d], d contiguous
__device__ __nv_bfloat16 g_wt_hi[(size_t)N_IN * KM * PC_DIM];         // 11.5 MB
__device__ __nv_bfloat16 g_wt_lo[(size_t)N_IN * KM * PC_DIM];

// ---------------- helpers ----------------
__device__ __forceinline__ void mma_bf16(float& c0, float& c1, float& c2, float& c3,
                                         unsigned a0, unsigned a1, unsigned a2, unsigned a3,
                                         unsigned b0, unsigned b1) {
    asm volatile(
        "mma.sync.aligned.m16n8k16.row.col.f32.bf16.bf16.f32 "
        "{%0,%1,%2,%3}, {%4,%5,%6,%7}, {%8,%9}, {%0,%1,%2,%3};\n"
        : "+f"(c0), "+f"(c1), "+f"(c2), "+f"(c3)
        : "r"(a0), "r"(a1), "r"(a2), "r"(a3), "r"(b0), "r"(b1));
}
__device__ __forceinline__ void ldmatrix_x4(unsigned& r0, unsigned& r1,
                                            unsigned& r2, unsigned& r3, uint32_t addr) {
    asm volatile("ldmatrix.sync.aligned.m8n8.x4.shared.b16 {%0,%1,%2,%3}, [%4];"
                 : "=r"(r0), "=r"(r1), "=r"(r2), "=r"(r3) : "r"(addr));
}
__device__ __forceinline__ void cp_async16(uint32_t dst, const void* src) {
    asm volatile("cp.async.cg.shared.global [%0], [%1], 16;\n" :: "r"(dst), "l"(src));
}
__device__ __forceinline__ void cp_commit() { asm volatile("cp.async.commit_group;\n"); }
__device__ __forceinline__ void cp_wait0() { asm volatile("cp.async.wait_group 0;\n" ::: "memory"); }
__device__ __forceinline__ void cp_wait1() { asm volatile("cp.async.wait_group 1;\n" ::: "memory"); }
__device__ __forceinline__ void cp_wait3() { asm volatile("cp.async.wait_group 3;\n" ::: "memory"); }

__device__ __forceinline__ float warp_sum(float v) {
    #pragma unroll
    for (int o = 16; o; o >>= 1) v += __shfl_xor_sync(0xffffffffu, v, o);
    return v;
}
__device__ __forceinline__ float warp_max(float v) {
    #pragma unroll
    for (int o = 16; o; o >>= 1) v = fmaxf(v, __shfl_xor_sync(0xffffffffu, v, o));
    return v;
}
__device__ __forceinline__ uint32_t smem_u32(const void* p) {
    return (uint32_t)__cvta_generic_to_shared(p);
}

// ---------------------------------------------------------------------------
// Decompose poses: x -> bf16 hi + lo
// ---------------------------------------------------------------------------
__global__ __launch_bounds__(256) void decomp_poses_kernel(
    const float* __restrict__ poses,
    __nv_bfloat16* __restrict__ hi, __nv_bfloat16* __restrict__ lo)
{
    const int i = blockIdx.x * 256 + threadIdx.x;
    const int n2 = B_SZ * POSE_STRIDE / 2;
    if (i >= n2) return;
    const float2 x = ((const float2*)poses)[i];
    const __nv_bfloat16 h0 = __float2bfloat16(x.x);
    const __nv_bfloat16 h1 = __float2bfloat16(x.y);
    const __nv_bfloat16 l0 = __float2bfloat16(x.x - __bfloat162float(h0));
    const __nv_bfloat16 l1 = __float2bfloat16(x.y - __bfloat162float(h1));
    ((__nv_bfloat162*)hi)[i] = __nv_bfloat162(h0, h1);
    ((__nv_bfloat162*)lo)[i] = __nv_bfloat162(l0, l1);
}

// ---------------------------------------------------------------------------
// Decompose + transpose w: w[n][d][km] f32 -> wt[n][km][d] bf16 hi/lo
// ---------------------------------------------------------------------------
__global__ __launch_bounds__(256) void decomp_wt_kernel(
    const float* __restrict__ w,
    __nv_bfloat16* __restrict__ hi, __nv_bfloat16* __restrict__ lo)
{
    __shared__ float tile[32][33];
    const int tx = threadIdx.x, ty = threadIdx.y;
    const int km0 = blockIdx.x * 32, d0 = blockIdx.y * 32, n = blockIdx.z;
    #pragma unroll
    for (int j = 0; j < 4; j++) {
        const int d = d0 + ty + 8 * j;
        tile[ty + 8 * j][tx] = w[((size_t)n * PC_DIM + d) * KM + km0 + tx];
    }
    __syncthreads();
    #pragma unroll
    for (int j = 0; j < 4; j++) {
        const int km = km0 + ty + 8 * j;
        const float x = tile[tx][ty + 8 * j];
        const __nv_bfloat16 h = __float2bfloat16(x);
        const __nv_bfloat16 l = __float2bfloat16(x - __bfloat162float(h));
        const size_t o = ((size_t)n * KM + km) * PC_DIM + d0 + tx;
        hi[o] = h;
        lo[o] = l;
    }
}

// ---------------------------------------------------------------------------
// Kernel A: bf16 3-term split GEMM, mma.sync + ldmatrix, kc-major tile reuse.
// grid (25, 32, 7), 256 threads, warp grid 2(M)x4(N), warp tile 64x32.
// K=256 in 4 chunks of 64; per chunk load {A_hi, A_lo, B_hi, B_lo} once and
// run 3 passes: (Ah,Bh), (Al,Bh), (Ah,Bl). 6 smem tile slots, 2 CTAs/SM.
// ---------------------------------------------------------------------------
#define PITCH 72                        // bf16 per smem row (144 B, ldmatrix CF)
#define TILE_BYTES (128 * PITCH * 2)    // 18432
#define VOTES_SMEM (6 * TILE_BYTES)     // 110592

__global__ __launch_bounds__(256, 2) void votes_hmma_kernel(
    const __nv_bfloat16* __restrict__ pa_hi,
    const __nv_bfloat16* __restrict__ pa_lo,
    const __nv_bfloat16* __restrict__ wt_hi,
    const __nv_bfloat16* __restrict__ wt_lo)
{
    extern __shared__ __nv_bfloat16 smem[];
    const uint32_t base = smem_u32(smem);
    // slots: A0,A1 (hi parity), A2,A3 (lo parity), BH, BL
    const uint32_t SLOT_BH = base + 4 * TILE_BYTES;
    const uint32_t SLOT_BL = base + 5 * TILE_BYTES;

    const int tid  = threadIdx.x;
    const int lane = tid & 31;
    const int wrp  = tid >> 5;
    const int wm   = wrp >> 2;        // 0..1
    const int wn   = wrp & 3;         // 0..3

    const int tn = blockIdx.x;        // 0..24
    const int tm = blockIdx.y;        // 0..31
    const int n  = blockIdx.z;        // 0..6

    // per-thread lane offsets (elements) for ldmatrix
    const int a_off = (((lane & 7) | (((lane >> 3) & 1) << 3)) * PITCH)
                    + ((lane >> 4) << 3) + wm * 64 * PITCH;
    const int b_off = (((lane & 7) | (((lane >> 4) & 1) << 3)) * PITCH)
                    + (((lane >> 3) & 1) << 3) + wn * 32 * PITCH;

    // staging decomposition: 1024 cp16 per tile, 4 per thread
    const int r_st = tid >> 1;                 // row pairs... (recomputed below)

    const __nv_bfloat16* Abase_h = pa_hi + (size_t)(tm * 128) * POSE_STRIDE + n * PC_DIM;
    const __nv_bfloat16* Abase_l = pa_lo + (size_t)(tm * 128) * POSE_STRIDE + n * PC_DIM;
    const __nv_bfloat16* Bbase_h = wt_hi + ((size_t)n * KM + tn * 128) * PC_DIM;
    const __nv_bfloat16* Bbase_l = wt_lo + ((size_t)n * KM + tn * 128) * PC_DIM;

    auto load_tile = [&](uint32_t dst, const __nv_bfloat16* src, int stride, int kc) {
        const __nv_bfloat16* s = src + kc * 64;
        #pragma unroll
        for (int i = 0; i < 4; i++) {
            const int idx = tid + 256 * i;
            const int r = idx >> 3, c = idx & 7;
            cp_async16(dst + (uint32_t)(r * PITCH * 2 + c * 16),
                       s + (size_t)r * stride + c * 8);
        }
        cp_commit();
    };
    (void)r_st;

    float acc[4][4][4];
    #pragma unroll
    for (int mi = 0; mi < 4; mi++)
        #pragma unroll
        for (int ni = 0; ni < 4; ni++)
            #pragma unroll
            for (int c = 0; c < 4; c++) acc[mi][ni][c] = 0.f;

    auto pass = [&](uint32_t Aslot, uint32_t Bslot) {
        #pragma unroll
        for (int ks = 0; ks < 4; ks++) {
            unsigned af[4][4];
            #pragma unroll
            for (int mi = 0; mi < 4; mi++)
                ldmatrix_x4(af[mi][0], af[mi][1], af[mi][2], af[mi][3],
                            Aslot + 2u * (uint32_t)(a_off + mi * 16 * PITCH + ks * 16));
            unsigned bf[4][2];
            #pragma unroll
            for (int p = 0; p < 2; p++)
                ldmatrix_x4(bf[2*p][0], bf[2*p][1], bf[2*p+1][0], bf[2*p+1][1],
                            Bslot + 2u * (uint32_t)(b_off + p * 16 * PITCH + ks * 16));
            #pragma unroll
            for (int mi = 0; mi < 4; mi++)
                #pragma unroll
                for (int ni = 0; ni < 4; ni++)
                    mma_bf16(acc[mi][ni][0], acc[mi][ni][1], acc[mi][ni][2], acc[mi][ni][3],
                             af[mi][0], af[mi][1], af[mi][2], af[mi][3],
                             bf[ni][0], bf[ni][1]);
        }
    };

    // prologue: kc=0 tiles (groups: ah0, al0, bh0, bl0)
    load_tile(base + 0 * TILE_BYTES, Abase_h, POSE_STRIDE, 0);
    load_tile(base + 2 * TILE_BYTES, Abase_l, POSE_STRIDE, 0);
    load_tile(SLOT_BH, Bbase_h, PC_DIM, 0);
    load_tile(SLOT_BL, Bbase_l, PC_DIM, 0);

    #pragma unroll 1
    for (int kc = 0; kc < 4; ++kc) {
        const uint32_t A_hi = base + (uint32_t)(kc & 1) * TILE_BYTES;
        const uint32_t A_lo = base + (uint32_t)(2 + (kc & 1)) * TILE_BYTES;
        if (kc < 3) {
            load_tile(base + (uint32_t)((kc + 1) & 1) * TILE_BYTES, Abase_h, POSE_STRIDE, kc + 1);
            load_tile(base + (uint32_t)(2 + ((kc + 1) & 1)) * TILE_BYTES, Abase_l, POSE_STRIDE, kc + 1);
        }
        if (kc < 3) cp_wait3(); else cp_wait1();
        __syncthreads();

        pass(A_hi, SLOT_BH);   // Ah*Bh
        pass(A_lo, SLOT_BH);   // Al*Bh
        __syncthreads();       // BH fully read

        if (kc < 3) load_tile(SLOT_BH, Bbase_h, PC_DIM, kc + 1);
        if (kc < 3) cp_wait3(); else cp_wait0();
        __syncthreads();

        pass(A_hi, SLOT_BL);   // Ah*Bl
        __syncthreads();       // BL + A slots fully read

        if (kc < 3) load_tile(SLOT_BL, Bbase_l, PC_DIM, kc + 1);
    }

    // epilogue (canonical D fragment layout)
    const int grp = lane >> 2, tig = lane & 3;
    #pragma unroll
    for (int mi = 0; mi < 4; mi++) {
        const int row = tm * 128 + wm * 64 + mi * 16 + grp;
        #pragma unroll
        for (int ni = 0; ni < 4; ni++) {
            const int col = tn * 128 + wn * 32 + ni * 8 + 2 * tig;
            float* p0 = g_votes + (size_t)row * VOTES_PER_B + n * KM + col;
            float* p1 = g_votes + (size_t)(row + 8) * VOTES_PER_B + n * KM + col;
            *(float2*)p0 = make_float2(acc[mi][ni][0], acc[mi][ni][1]);
            *(float2*)p1 = make_float2(acc[mi][ni][2], acc[mi][ni][3]);
        }
    }
}

// ---------------------------------------------------------------------------
// Kernel B: register-resident routing. 148 CTAs x 800 threads (25 warps).
// ---------------------------------------------------------------------------
#define RT_GRID 148

__global__ __launch_bounds__(800, 1) void routing_kernel(
    const float* __restrict__ acts_prior,
    const float* __restrict__ ln_gamma,
    const float* __restrict__ ln_beta,
    const float* __restrict__ cls_weight,
    const float* __restrict__ cls_bias,
    float* __restrict__ out)
{
    __shared__ float sa[8];
    __shared__ float sagree[184];
    __shared__ float sra[184];

    const int tid  = threadIdx.x;
    const int wrp  = tid >> 5;
    const int lane = tid & 31;
    const int k    = wrp;

    const float4 g4  = *(const float4*)&ln_gamma[lane * 4];
    const float4 b4  = *(const float4*)&ln_beta[lane * 4];
    const float4 cw4 = *(const float4*)&cls_weight[k * MC_DIM + lane * 4];
    const float  bias = cls_bias[k];

    #pragma unroll 1
    for (int b = blockIdx.x; b < B_SZ; b += RT_GRID) {
        if (tid < N_IN) sa[tid] = acts_prior[(size_t)b * N_IN + tid];

        float4 v[N_IN];
        {
            const float* vb = g_votes + (size_t)b * VOTES_PER_B + k * MC_DIM + lane * 4;
            #pragma unroll
            for (int n = 0; n < N_IN; n++)
                v[n] = *(const float4*)(vb + n * KM);
        }
        __syncthreads();

        float ra[N_IN];
        #pragma unroll
        for (int n = 0; n < N_IN; n++) ra[n] = sa[n] * (1.f / 25.f);

        float4 pose;
        #pragma unroll 1
        for (int it = 0; it < 3; ++it) {
            if (it > 0) {
                #pragma unroll
                for (int n = 0; n < N_IN; n++) {
                    float d = v[n].x * pose.x + v[n].y * pose.y
                            + v[n].z * pose.z + v[n].w * pose.w;
                    d = warp_sum(d);
                    if (lane == 0) sagree[n * K_CAPS + k] = d * AGREE_SCALE;
                }
                __syncthreads();
                if (wrp < N_IN) {
                    const float x = (lane < K_CAPS) ? sagree[wrp * K_CAPS + lane] : -1e30f;
                    const float mx = warp_max(x);
                    const float e = (lane < K_CAPS) ? __expf(x - mx) : 0.f;
                    const float ssum = warp_sum(e);
                    if (lane < K_CAPS) {
                        const float r = e / ssum;
                        sra[wrp * K_CAPS + lane] = r * sa[wrp];
                        if (it == 2)
                            out[(size_t)B_SZ * K_CAPS + (size_t)b * 175
                                + wrp * K_CAPS + lane] = r;
                    }
                }
                __syncthreads();
                #pragma unroll
                for (int n = 0; n < N_IN; n++) ra[n] = sra[n * K_CAPS + k];
            }
            pose = make_float4(0.f, 0.f, 0.f, 0.f);
            #pragma unroll
            for (int n = 0; n < N_IN; n++) {
                pose.x = fmaf(ra[n], v[n].x, pose.x);
                pose.y = fmaf(ra[n], v[n].y, pose.y);
                pose.z = fmaf(ra[n], v[n].z, pose.z);
                pose.w = fmaf(ra[n], v[n].w, pose.w);
            }
            {
                float s = pose.x + pose.y + pose.z + pose.w;
                s = warp_sum(s);
                const float mu = s * (1.f / 128.f);
                float var = (pose.x - mu) * (pose.x - mu) + (pose.y - mu) * (pose.y - mu)
                          + (pose.z - mu) * (pose.z - mu) + (pose.w - mu) * (pose.w - mu);
                var = warp_sum(var) * (1.f / 128.f);
                const float rs = rsqrtf(var + LN_EPS);
                pose.x = (pose.x - mu) * rs * g4.x + b4.x;
                pose.y = (pose.y - mu) * rs * g4.y + b4.y;
                pose.z = (pose.z - mu) * rs * g4.z + b4.z;
                pose.w = (pose.w - mu) * rs * g4.w + b4.w;
            }
        }
        {
            float d = pose.x * cw4.x + pose.y * cw4.y + pose.z * cw4.z + pose.w * cw4.w;
            d = warp_sum(d);
            if (lane == 0) out[(size_t)b * K_CAPS + k] = d + bias;
        }
    }
}

// ---------------------------------------------------------------------------
extern "C" void kernel_launch(void* const* d_in, const int* in_sizes, int n_in,
                              void* d_out, int out_size)
{
    (void)in_sizes; (void)n_in; (void)out_size;
    const float* poses = (const float*)d_in[0];
    const float* acts  = (const float*)d_in[1];
    const float* w     = (const float*)d_in[2];
    const float* gamma = (const float*)d_in[3];
    const float* beta  = (const float*)d_in[4];
    const float* clsw  = (const float*)d_in[5];
    const float* clsb  = (const float*)d_in[6];
    float* out = (float*)d_out;

    __nv_bfloat16 *pa_hi, *pa_lo, *wt_hi, *wt_lo;
    cudaGetSymbolAddress((void**)&pa_hi, g_pa_hi);
    cudaGetSymbolAddress((void**)&pa_lo, g_pa_lo);
    cudaGetSymbolAddress((void**)&wt_hi, g_wt_hi);
    cudaGetSymbolAddress((void**)&wt_lo, g_wt_lo);

    {
        const int n2 = B_SZ * POSE_STRIDE / 2;
        decomp_poses_kernel<<<(n2 + 255) / 256, 256>>>(poses, pa_hi, pa_lo);
        decomp_wt_kernel<<<dim3(KM / 32, PC_DIM / 32, N_IN), dim3(32, 8)>>>(w, wt_hi, wt_lo);
    }

    cudaFuncSetAttribute(votes_hmma_kernel,
                         cudaFuncAttributeMaxDynamicSharedMemorySize,
                         VOTES_SMEM);
    votes_hmma_kernel<<<dim3(25, 32, 7), 256, VOTES_SMEM>>>(pa_hi, pa_lo, wt_hi, wt_lo);

    routing_kernel<<<RT_GRID, 800>>>(acts, gamma, beta, clsw, clsb, out);
}